// round 13
// baseline (speedup 1.0000x reference)
#include <cuda_runtime.h>

// AvgPool2d 64x64, stride 1, replicate edge-pad. x: (16,64,256,256) fp32.
// FINAL KERNEL (v3, best of 12-round series: 94.2 us wall / 90.6 us ncu).
//
// Structure: one CTA per (n,c) image, 16-batch software pipeline.
//  - Phase 1 (all 16 warps): per-row 64-wide horizontal window sums computed
//    ENTIRELY in registers — 8-elem local prefix, 5-step shfl warp scan,
//    cross-lane shfl differences H[j] = P[j+63] - P[j-1] — stored to a
//    96-row smem ring via two STS.128 per lane. Next batch's row is
//    prefetched into registers before the scan, keeping DRAM reads in
//    flight through scan/stores/vertical/barrier.
//  - Phase 2 (threads 0..255): per-output-column vertical sliding 64-window
//    over the ring (odd-ish stride 196 avoids bank conflicts on column
//    walks), coalesced row writes, replicate-pad edges from box 0 / box 192.
//  - One __syncthreads per batch; ring slack (96 = 64 + 16 + 16) makes
//    store(bt+1) disjoint from read(bt) slots.
//
// Measured ceiling: 5.9 TB/s effective mixed R/W (536 MB in 90.6 us), DRAM
// 66% / L1 73% / nothing saturated. Falsified alternatives: 512-thread
// vertical split, streaming cache hints, 32-row batches, 3 CTAs/SM,
// producer/consumer warp specialization, tail-wave shaping, TMA bulk stores.

#define IMG_ELEMS 65536        // 256*256
#define HSTR 196               // 196 ≡ 0 mod 4 -> float4-aligned H rows
#define RING 96                // 64-row window + 16-row batch + 16 slack
#define SMEM_BYTES (RING * HSTR * 4)   // 75264 B -> 2 CTAs/SM

__global__ __launch_bounds__(512, 2)
void avgpool64_final(const float* __restrict__ x, float* __restrict__ out) {
    extern __shared__ float Hs[];                 // [RING][HSTR]

    const int tid  = threadIdx.x;
    const int wid  = tid >> 5;
    const int lane = tid & 31;

    const float* img    = x   + (size_t)blockIdx.x * IMG_ELEMS;
    float*       outImg = out + (size_t)blockIdx.x * IMG_ELEMS;

    // vertical state (threads 0..255 own output column tid)
    int cj = tid - 31;
    cj = cj < 0 ? 0 : (cj > 192 ? 192 : cj);
    float vs = 0.0f;
    const float inv = 1.0f / 4096.0f;

    const float4* rp = (const float4*)img;        // 64 float4 per image row
    float4 a = rp[wid * 64 + lane * 2];
    float4 b = rp[wid * 64 + lane * 2 + 1];

    int base = 0;                                 // (16*bt) % RING
    #pragma unroll 1
    for (int bt = 0; bt < 16; ++bt) {
        const int r = bt * 16 + wid;              // this warp's input row

        // local inclusive prefix over this lane's 8 values
        float p0 = a.x;
        float p1 = p0 + a.y;
        float p2 = p1 + a.z;
        float p3 = p2 + a.w;
        float p4 = p3 + b.x;
        float p5 = p4 + b.y;
        float p6 = p5 + b.z;
        float p7 = p6 + b.w;

        // prefetch next batch's row ASAP (a,b dead) -> DRAM reads in flight
        // through scan + shuffles + stores + vertical
        if (bt < 15) {
            a = rp[(r + 16) * 64 + lane * 2];
            b = rp[(r + 16) * 64 + lane * 2 + 1];
        }

        // warp inclusive scan of lane totals
        float t = p7;
        #pragma unroll
        for (int o = 1; o < 32; o <<= 1) {
            float u = __shfl_up_sync(0xffffffffu, t, o);
            if (lane >= o) t += u;
        }
        const float e = t - p7;                   // global prefix at 8*lane-1

        // global inclusive prefixes q_k = P[8*lane+k]
        float q0 = e + p0, q1 = e + p1, q2 = e + p2, q3 = e + p3;
        float q4 = e + p4, q5 = e + p5, q6 = e + p6, q7 = e + p7;

        // H[j] = P[j+63] - P[j-1] via cross-lane differences:
        //   H[8l]   = q7(lane l+7) - e
        //   H[8l+k] = q_{k-1}(lane l+8) - q_{k-1},  k=1..7
        // lane 24's h0 = t31 - t23 = H[192].
        float s7 = __shfl_down_sync(0xffffffffu, q7, 7);
        float s0 = __shfl_down_sync(0xffffffffu, q0, 8);
        float s1 = __shfl_down_sync(0xffffffffu, q1, 8);
        float s2 = __shfl_down_sync(0xffffffffu, q2, 8);
        float s3 = __shfl_down_sync(0xffffffffu, q3, 8);
        float s4 = __shfl_down_sync(0xffffffffu, q4, 8);
        float s5 = __shfl_down_sync(0xffffffffu, q5, 8);
        float s6 = __shfl_down_sync(0xffffffffu, q6, 8);

        float h0 = s7 - e;
        float h1 = s0 - q0;
        float h2 = s1 - q1;
        float h3 = s2 - q2;
        float h4 = s3 - q3;
        float h5 = s4 - q4;
        float h6 = s5 - q5;
        float h7 = s6 - q6;

        float* Hrow = Hs + (base + wid) * HSTR;
        if (lane < 24) {
            float4 v0 = make_float4(h0, h1, h2, h3);
            float4 v1 = make_float4(h4, h5, h6, h7);
            float4* hp = (float4*)(Hrow + 8 * lane);
            hp[0] = v0;
            hp[1] = v1;
        } else if (lane == 24) {
            Hrow[192] = h0;
        }

        __syncthreads();   // H rows of batch bt visible; fences vertical(bt-1)

        // ------- vertical sliding window: 16 steps, threads 0..255 -------
        if (tid < 256) {
            const float* Hn = Hs + base * HSTR + cj;        // new rows
            if (bt < 4) {
                #pragma unroll
                for (int k = 0; k < 16; ++k)
                    vs += Hn[k * HSTR];
                if (bt == 3) {                    // vs = box[0]; y = 0..31
                    float v = vs * inv;
                    #pragma unroll
                    for (int y = 0; y < 32; ++y)
                        outImg[y * 256 + tid] = v;
                }
            } else {
                int sob = base + 32;                         // row r-64 slots
                if (sob >= RING) sob -= RING;                // never splits batch
                const float* Ho = Hs + sob * HSTR + cj;
                float* op = outImg + (bt * 16 - 32) * 256 + tid;
                #pragma unroll
                for (int k = 0; k < 16; ++k) {
                    vs += Hn[k * HSTR] - Ho[k * HSTR];
                    op[k * 256] = vs * inv;
                }
                if (bt == 15) {                   // vs = box[192]; y = 224..255
                    float v = vs * inv;
                    #pragma unroll
                    for (int y = 224; y < 256; ++y)
                        outImg[y * 256 + tid] = v;
                }
            }
        }

        base += 16;
        if (base >= RING) base -= RING;
    }
}

extern "C" void kernel_launch(void* const* d_in, const int* in_sizes, int n_in,
                              void* d_out, int out_size) {
    const float* x = (const float*)d_in[0];
    float* out = (float*)d_out;
    const int n_images = in_sizes[0] / IMG_ELEMS;   // 16*64 = 1024

    cudaFuncSetAttribute(avgpool64_final,
                         cudaFuncAttributeMaxDynamicSharedMemorySize, SMEM_BYTES);
    avgpool64_final<<<n_images, 512, SMEM_BYTES>>>(x, out);
}

// round 15
// speedup vs baseline: 1.0105x; 1.0105x over previous
#include <cuda_runtime.h>

// AvgPool2d 64x64, stride 1, replicate edge-pad. x: (16,64,256,256) fp32.
// FINAL KERNEL (v3; best of 14-round series: 94.2 us wall / 90.5 us ncu,
// reproduced 4x; R14 was an infra failure, source unchanged).
// 268 MB in + 268 MB out in 90.5 us = 5.9 TB/s effective.
//
// Structure: one CTA per (n,c) image, 16-batch software pipeline.
//  - Phase 1 (all 16 warps): per-row 64-wide horizontal window sums computed
//    ENTIRELY in registers — 8-elem local prefix, 5-step shfl warp scan,
//    cross-lane shfl differences H[j] = P[j+63] - P[j-1] — stored to a
//    96-row smem ring via two STS.128 per lane. Next batch's row is
//    prefetched into registers before the scan, keeping DRAM reads in
//    flight through scan/stores/vertical/barrier.
//  - Phase 2 (threads 0..255): per-output-column vertical sliding 64-window
//    over the ring (stride 196 keeps column walks conflict-free), coalesced
//    row writes, replicate-pad edges emitted from box 0 / box 192.
//  - One __syncthreads per batch; ring slack (96 = 64 + 16 + 16) makes
//    store(bt+1) slots disjoint from read(bt) slots.
//
// Falsified alternatives (all neutral or regressive, ncu-verified):
// 512-thread vertical split, streaming cache hints (clean A/B), 32-row
// batches, 3 CTAs/SM, producer/consumer warp specialization, tail-wave
// shaping, TMA bulk stores. Plateau signature: DRAM 66% / L1 72% / L2 34%,
// nothing saturated -> mixed fine-grained R/W stream at the memory system's
// practical ceiling on this part.

#define IMG_ELEMS 65536        // 256*256
#define HSTR 196               // 196 ≡ 0 mod 4 -> float4-aligned H rows
#define RING 96                // 64-row window + 16-row batch + 16 slack
#define SMEM_BYTES (RING * HSTR * 4)   // 75264 B -> 2 CTAs/SM

__global__ __launch_bounds__(512, 2)
void avgpool64_final(const float* __restrict__ x, float* __restrict__ out) {
    extern __shared__ float Hs[];                 // [RING][HSTR]

    const int tid  = threadIdx.x;
    const int wid  = tid >> 5;
    const int lane = tid & 31;

    const float* img    = x   + (size_t)blockIdx.x * IMG_ELEMS;
    float*       outImg = out + (size_t)blockIdx.x * IMG_ELEMS;

    // vertical state (threads 0..255 own output column tid)
    int cj = tid - 31;
    cj = cj < 0 ? 0 : (cj > 192 ? 192 : cj);
    float vs = 0.0f;
    const float inv = 1.0f / 4096.0f;

    const float4* rp = (const float4*)img;        // 64 float4 per image row
    float4 a = rp[wid * 64 + lane * 2];
    float4 b = rp[wid * 64 + lane * 2 + 1];

    int base = 0;                                 // (16*bt) % RING
    #pragma unroll 1
    for (int bt = 0; bt < 16; ++bt) {
        const int r = bt * 16 + wid;              // this warp's input row

        // local inclusive prefix over this lane's 8 values
        float p0 = a.x;
        float p1 = p0 + a.y;
        float p2 = p1 + a.z;
        float p3 = p2 + a.w;
        float p4 = p3 + b.x;
        float p5 = p4 + b.y;
        float p6 = p5 + b.z;
        float p7 = p6 + b.w;

        // prefetch next batch's row ASAP (a,b dead) -> DRAM reads in flight
        // through scan + shuffles + stores + vertical
        if (bt < 15) {
            a = rp[(r + 16) * 64 + lane * 2];
            b = rp[(r + 16) * 64 + lane * 2 + 1];
        }

        // warp inclusive scan of lane totals
        float t = p7;
        #pragma unroll
        for (int o = 1; o < 32; o <<= 1) {
            float u = __shfl_up_sync(0xffffffffu, t, o);
            if (lane >= o) t += u;
        }
        const float e = t - p7;                   // global prefix at 8*lane-1

        // global inclusive prefixes q_k = P[8*lane+k]
        float q0 = e + p0, q1 = e + p1, q2 = e + p2, q3 = e + p3;
        float q4 = e + p4, q5 = e + p5, q6 = e + p6, q7 = e + p7;

        // H[j] = P[j+63] - P[j-1] via cross-lane differences:
        //   H[8l]   = q7(lane l+7) - e
        //   H[8l+k] = q_{k-1}(lane l+8) - q_{k-1},  k=1..7
        // lane 24's h0 = t31 - t23 = H[192].
        float s7 = __shfl_down_sync(0xffffffffu, q7, 7);
        float s0 = __shfl_down_sync(0xffffffffu, q0, 8);
        float s1 = __shfl_down_sync(0xffffffffu, q1, 8);
        float s2 = __shfl_down_sync(0xffffffffu, q2, 8);
        float s3 = __shfl_down_sync(0xffffffffu, q3, 8);
        float s4 = __shfl_down_sync(0xffffffffu, q4, 8);
        float s5 = __shfl_down_sync(0xffffffffu, q5, 8);
        float s6 = __shfl_down_sync(0xffffffffu, q6, 8);

        float h0 = s7 - e;
        float h1 = s0 - q0;
        float h2 = s1 - q1;
        float h3 = s2 - q2;
        float h4 = s3 - q3;
        float h5 = s4 - q4;
        float h6 = s5 - q5;
        float h7 = s6 - q6;

        float* Hrow = Hs + (base + wid) * HSTR;
        if (lane < 24) {
            float4 v0 = make_float4(h0, h1, h2, h3);
            float4 v1 = make_float4(h4, h5, h6, h7);
            float4* hp = (float4*)(Hrow + 8 * lane);
            hp[0] = v0;
            hp[1] = v1;
        } else if (lane == 24) {
            Hrow[192] = h0;
        }

        __syncthreads();   // H rows of batch bt visible; fences vertical(bt-1)

        // ------- vertical sliding window: 16 steps, threads 0..255 -------
        if (tid < 256) {
            const float* Hn = Hs + base * HSTR + cj;        // new rows
            if (bt < 4) {
                #pragma unroll
                for (int k = 0; k < 16; ++k)
                    vs += Hn[k * HSTR];
                if (bt == 3) {                    // vs = box[0]; y = 0..31
                    float v = vs * inv;
                    #pragma unroll
                    for (int y = 0; y < 32; ++y)
                        outImg[y * 256 + tid] = v;
                }
            } else {
                int sob = base + 32;                         // row r-64 slots
                if (sob >= RING) sob -= RING;                // never splits batch
                const float* Ho = Hs + sob * HSTR + cj;
                float* op = outImg + (bt * 16 - 32) * 256 + tid;
                #pragma unroll
                for (int k = 0; k < 16; ++k) {
                    vs += Hn[k * HSTR] - Ho[k * HSTR];
                    op[k * 256] = vs * inv;
                }
                if (bt == 15) {                   // vs = box[192]; y = 224..255
                    float v = vs * inv;
                    #pragma unroll
                    for (int y = 224; y < 256; ++y)
                        outImg[y * 256 + tid] = v;
                }
            }
        }

        base += 16;
        if (base >= RING) base -= RING;
    }
}

extern "C" void kernel_launch(void* const* d_in, const int* in_sizes, int n_in,
                              void* d_out, int out_size) {
    const float* x = (const float*)d_in[0];
    float* out = (float*)d_out;
    const int n_images = in_sizes[0] / IMG_ELEMS;   // 16*64 = 1024

    cudaFuncSetAttribute(avgpool64_final,
                         cudaFuncAttributeMaxDynamicSharedMemorySize, SMEM_BYTES);
    avgpool64_final<<<n_images, 512, SMEM_BYTES>>>(x, out);
}

// round 16
// speedup vs baseline: 1.0109x; 1.0003x over previous
#include <cuda_runtime.h>

// AvgPool2d 64x64, stride 1, replicate edge-pad. x: (16,64,256,256) fp32.
// FINAL KERNEL (v3; best of 15-round series: 94.2 us wall / 90.1 us ncu,
// reproduced 5x). 268 MB in + 268 MB out in 90.1 us = 5.9 TB/s effective.
//
// Structure: one CTA per (n,c) image, 16-batch software pipeline.
//  - Phase 1 (all 16 warps): per-row 64-wide horizontal window sums computed
//    ENTIRELY in registers — 8-elem local prefix, 5-step shfl warp scan,
//    cross-lane shfl differences H[j] = P[j+63] - P[j-1] — stored to a
//    96-row smem ring via two STS.128 per lane. Next batch's row is
//    prefetched into registers before the scan, keeping DRAM reads in
//    flight through scan/stores/vertical/barrier.
//  - Phase 2 (threads 0..255): per-output-column vertical sliding 64-window
//    over the ring (stride 196 keeps column walks conflict-free), coalesced
//    row writes, replicate-pad edges emitted from box 0 / box 192.
//  - One __syncthreads per batch; ring slack (96 = 64 + 16 + 16) makes
//    store(bt+1) slots disjoint from read(bt) slots.
//
// Falsified alternatives (all neutral or regressive, ncu-verified):
// 512-thread vertical split, streaming cache hints (clean A/B), 32-row
// batches, 3 CTAs/SM, producer/consumer warp specialization, tail-wave
// shaping, TMA bulk stores. Plateau signature: DRAM 66% / L1 73% / L2 34%,
// nothing saturated -> minimal-traffic fine-grained mixed R/W stream at the
// memory system's practical scheduling ceiling on this part.

#define IMG_ELEMS 65536        // 256*256
#define HSTR 196               // 196 ≡ 0 mod 4 -> float4-aligned H rows
#define RING 96                // 64-row window + 16-row batch + 16 slack
#define SMEM_BYTES (RING * HSTR * 4)   // 75264 B -> 2 CTAs/SM

__global__ __launch_bounds__(512, 2)
void avgpool64_final(const float* __restrict__ x, float* __restrict__ out) {
    extern __shared__ float Hs[];                 // [RING][HSTR]

    const int tid  = threadIdx.x;
    const int wid  = tid >> 5;
    const int lane = tid & 31;

    const float* img    = x   + (size_t)blockIdx.x * IMG_ELEMS;
    float*       outImg = out + (size_t)blockIdx.x * IMG_ELEMS;

    // vertical state (threads 0..255 own output column tid)
    int cj = tid - 31;
    cj = cj < 0 ? 0 : (cj > 192 ? 192 : cj);
    float vs = 0.0f;
    const float inv = 1.0f / 4096.0f;

    const float4* rp = (const float4*)img;        // 64 float4 per image row
    float4 a = rp[wid * 64 + lane * 2];
    float4 b = rp[wid * 64 + lane * 2 + 1];

    int base = 0;                                 // (16*bt) % RING
    #pragma unroll 1
    for (int bt = 0; bt < 16; ++bt) {
        const int r = bt * 16 + wid;              // this warp's input row

        // local inclusive prefix over this lane's 8 values
        float p0 = a.x;
        float p1 = p0 + a.y;
        float p2 = p1 + a.z;
        float p3 = p2 + a.w;
        float p4 = p3 + b.x;
        float p5 = p4 + b.y;
        float p6 = p5 + b.z;
        float p7 = p6 + b.w;

        // prefetch next batch's row ASAP (a,b dead) -> DRAM reads in flight
        // through scan + shuffles + stores + vertical
        if (bt < 15) {
            a = rp[(r + 16) * 64 + lane * 2];
            b = rp[(r + 16) * 64 + lane * 2 + 1];
        }

        // warp inclusive scan of lane totals
        float t = p7;
        #pragma unroll
        for (int o = 1; o < 32; o <<= 1) {
            float u = __shfl_up_sync(0xffffffffu, t, o);
            if (lane >= o) t += u;
        }
        const float e = t - p7;                   // global prefix at 8*lane-1

        // global inclusive prefixes q_k = P[8*lane+k]
        float q0 = e + p0, q1 = e + p1, q2 = e + p2, q3 = e + p3;
        float q4 = e + p4, q5 = e + p5, q6 = e + p6, q7 = e + p7;

        // H[j] = P[j+63] - P[j-1] via cross-lane differences:
        //   H[8l]   = q7(lane l+7) - e
        //   H[8l+k] = q_{k-1}(lane l+8) - q_{k-1},  k=1..7
        // lane 24's h0 = t31 - t23 = H[192].
        float s7 = __shfl_down_sync(0xffffffffu, q7, 7);
        float s0 = __shfl_down_sync(0xffffffffu, q0, 8);
        float s1 = __shfl_down_sync(0xffffffffu, q1, 8);
        float s2 = __shfl_down_sync(0xffffffffu, q2, 8);
        float s3 = __shfl_down_sync(0xffffffffu, q3, 8);
        float s4 = __shfl_down_sync(0xffffffffu, q4, 8);
        float s5 = __shfl_down_sync(0xffffffffu, q5, 8);
        float s6 = __shfl_down_sync(0xffffffffu, q6, 8);

        float h0 = s7 - e;
        float h1 = s0 - q0;
        float h2 = s1 - q1;
        float h3 = s2 - q2;
        float h4 = s3 - q3;
        float h5 = s4 - q4;
        float h6 = s5 - q5;
        float h7 = s6 - q6;

        float* Hrow = Hs + (base + wid) * HSTR;
        if (lane < 24) {
            float4 v0 = make_float4(h0, h1, h2, h3);
            float4 v1 = make_float4(h4, h5, h6, h7);
            float4* hp = (float4*)(Hrow + 8 * lane);
            hp[0] = v0;
            hp[1] = v1;
        } else if (lane == 24) {
            Hrow[192] = h0;
        }

        __syncthreads();   // H rows of batch bt visible; fences vertical(bt-1)

        // ------- vertical sliding window: 16 steps, threads 0..255 -------
        if (tid < 256) {
            const float* Hn = Hs + base * HSTR + cj;        // new rows
            if (bt < 4) {
                #pragma unroll
                for (int k = 0; k < 16; ++k)
                    vs += Hn[k * HSTR];
                if (bt == 3) {                    // vs = box[0]; y = 0..31
                    float v = vs * inv;
                    #pragma unroll
                    for (int y = 0; y < 32; ++y)
                        outImg[y * 256 + tid] = v;
                }
            } else {
                int sob = base + 32;                         // row r-64 slots
                if (sob >= RING) sob -= RING;                // never splits batch
                const float* Ho = Hs + sob * HSTR + cj;
                float* op = outImg + (bt * 16 - 32) * 256 + tid;
                #pragma unroll
                for (int k = 0; k < 16; ++k) {
                    vs += Hn[k * HSTR] - Ho[k * HSTR];
                    op[k * 256] = vs * inv;
                }
                if (bt == 15) {                   // vs = box[192]; y = 224..255
                    float v = vs * inv;
                    #pragma unroll
                    for (int y = 224; y < 256; ++y)
                        outImg[y * 256 + tid] = v;
                }
            }
        }

        base += 16;
        if (base >= RING) base -= RING;
    }
}

extern "C" void kernel_launch(void* const* d_in, const int* in_sizes, int n_in,
                              void* d_out, int out_size) {
    const float* x = (const float*)d_in[0];
    float* out = (float*)d_out;
    const int n_images = in_sizes[0] / IMG_ELEMS;   // 16*64 = 1024

    cudaFuncSetAttribute(avgpool64_final,
                         cudaFuncAttributeMaxDynamicSharedMemorySize, SMEM_BYTES);
    avgpool64_final<<<n_images, 512, SMEM_BYTES>>>(x, out);
}